// round 2
// baseline (speedup 1.0000x reference)
#include <cuda_runtime.h>
#include <math.h>

#define TOKENS 32768
#define LSEQ   512
#define HID    128
#define VD     256
#define FFND   256
#define QKN    768   // 128 Q | 128 K | 256 V | 256 G

__device__ float g_X [TOKENS * HID];
__device__ float g_Xn[TOKENS * HID];
__device__ float g_Y1[TOKENS * HID];
__device__ float g_QK[(size_t)TOKENS * QKN];
__device__ float g_P [TOKENS * VD];
__device__ float g_Hf[TOKENS * FFND];
__device__ float g_W [4 * HID * QKN];
__device__ float g_qc[LSEQ * 16], g_qs[LSEQ * 16], g_kc[LSEQ * 16], g_ks[LSEQ * 16];

__device__ __forceinline__ float geluf(float v){ return 0.5f*v*(1.0f+erff(v*0.70710678f)); }
__device__ __forceinline__ float siluf(float v){ return v/(1.0f+expf(-v)); }

// ------------------- xpos tables -------------------
__global__ void xpos_table_kernel(){
    int idx = blockIdx.x*256 + threadIdx.x;
    if (idx >= LSEQ*16) return;
    int l = idx >> 4, j = idx & 15;
    float base = ((float)j + 12.8f) / 44.8f;          // (j+0.4*32)/(1.4*32)
    float sc   = powf(base, (float)l / 512.0f);
    float ang  = (float)l * powf(10000.0f, -(float)j/16.0f);
    float s, c; sincosf(ang, &s, &c);
    g_qc[idx]=c*sc; g_qs[idx]=s*sc; g_kc[idx]=c/sc; g_ks[idx]=s/sc;
}

// ------------------- pack QKVG weights: [4][128][768] -------------------
__global__ void pack_w_kernel(const float* __restrict__ wq, const float* __restrict__ wk,
                              const float* __restrict__ wv, const float* __restrict__ wg){
    int idx = blockIdx.x*256 + threadIdx.x;
    if (idx >= 4*HID*QKN) return;
    int l = idx/(HID*QKN), r = idx%(HID*QKN), hrow = r/QKN, c = r%QKN;
    float v;
    if (c < 128)      v = wq[(((size_t)l*4 + (c>>5))*HID + hrow)*32 + (c&31)];
    else if (c < 256) { int cc=c-128; v = wk[(((size_t)l*4 + (cc>>5))*HID + hrow)*32 + (cc&31)]; }
    else if (c < 512) { int cc=c-256; v = wv[(((size_t)l*4 + (cc>>6))*HID + hrow)*64 + (cc&63)]; }
    else              v = wg[((size_t)l*HID + hrow)*VD + (c-512)];
    g_W[idx] = v;
}

// ------------------- input MLP -------------------
__global__ __launch_bounds__(256) void rem_kernel(
    const float* __restrict__ x,
    const float* __restrict__ w1, const float* __restrict__ b1,
    const float* __restrict__ w2, const float* __restrict__ b2,
    const float* __restrict__ w3, const float* __restrict__ b3,
    float* __restrict__ X)
{
    __shared__ float sw1[160], sb1[32], sw2[2048], sb2[64], sw3[8192], sb3[128];
    int tid = threadIdx.x;
    for (int i=tid;i<160; i+=256) sw1[i]=w1[i];
    for (int i=tid;i<2048;i+=256) sw2[i]=w2[i];
    for (int i=tid;i<8192;i+=256) sw3[i]=w3[i];
    if (tid<32)  sb1[tid]=b1[tid];
    if (tid<64)  sb2[tid]=b2[tid];
    if (tid<128) sb3[tid]=b3[tid];
    __syncthreads();
    int t = blockIdx.x*256 + tid;
    float xin[5];
#pragma unroll
    for (int k=0;k<5;k++) xin[k] = x[(size_t)t*5+k];
    float h1[32];
#pragma unroll
    for (int o=0;o<32;o++){ float s=sb1[o];
#pragma unroll
        for (int k=0;k<5;k++) s += xin[k]*sw1[k*32+o];
        h1[o]=geluf(s); }
    float h2[64];
#pragma unroll
    for (int o=0;o<64;o++){ float s=sb2[o];
#pragma unroll
        for (int k=0;k<32;k++) s += h1[k]*sw2[k*64+o];
        h2[o]=geluf(s); }
    for (int o=0;o<128;o+=4){
        float v0=sb3[o],v1=sb3[o+1],v2=sb3[o+2],v3=sb3[o+3];
#pragma unroll
        for (int k=0;k<64;k++){ float hk=h2[k];
            v0+=hk*sw3[k*128+o]; v1+=hk*sw3[k*128+o+1];
            v2+=hk*sw3[k*128+o+2]; v3+=hk*sw3[k*128+o+3]; }
        *(float4*)(X+(size_t)t*128+o) = make_float4(geluf(v0),geluf(v1),geluf(v2),geluf(v3));
    }
}

// ------------------- LayerNorm(128), 1 warp / token -------------------
__global__ __launch_bounds__(256) void ln_kernel(
    const float* __restrict__ X, const float* __restrict__ w,
    const float* __restrict__ b, float* __restrict__ Y)
{
    int g = blockIdx.x*256 + threadIdx.x;
    int row = g>>5, lane = g&31;
    float4 v = *(const float4*)(X + (size_t)row*128 + lane*4);
    float s = v.x+v.y+v.z+v.w;
    float s2 = v.x*v.x+v.y*v.y+v.z*v.z+v.w*v.w;
#pragma unroll
    for (int o=16;o;o>>=1){ s += __shfl_xor_sync(~0u,s,o); s2 += __shfl_xor_sync(~0u,s2,o); }
    float mean = s*(1.f/128.f), var = s2*(1.f/128.f)-mean*mean;
    float rstd = rsqrtf(var + 1e-5f);
    float4 wv = *(const float4*)(w+lane*4), bv = *(const float4*)(b+lane*4), r;
    r.x=(v.x-mean)*rstd*wv.x+bv.x; r.y=(v.y-mean)*rstd*wv.y+bv.y;
    r.z=(v.z-mean)*rstd*wv.z+bv.z; r.w=(v.w-mean)*rstd*wv.w+bv.w;
    *(float4*)(Y + (size_t)row*128 + lane*4) = r;
}

// ------------------- GEMM 128x64x16, OP: 0 none, 1 gelu, 2 xpos, 3 residual -------------------
template <int OP>
__global__ __launch_bounds__(256) void gemm_kernel(
    const float* __restrict__ A, const float* __restrict__ B,
    const float* __restrict__ bias, const float* __restrict__ R,
    float* __restrict__ C, int M, int N, int K)
{
    __shared__ float As[16][132];
    __shared__ float Bs[16][64];
    const int tid = threadIdx.x, tx = tid&15, ty = tid>>4;
    const int m0 = blockIdx.y*128, n0 = blockIdx.x*64;
    float acc[8][4] = {};
    const int ar = tid>>2, ac = (tid&3)*4, br = tid>>4, bc = (tid&15)*4;

    for (int k0=0; k0<K; k0+=16){
#pragma unroll
        for (int rr=0; rr<2; rr++){
            int row = ar + rr*64;
            float4 v = *(const float4*)(A + (size_t)(m0+row)*K + k0 + ac);
            As[ac+0][row]=v.x; As[ac+1][row]=v.y; As[ac+2][row]=v.z; As[ac+3][row]=v.w;
        }
        *(float4*)&Bs[br][bc] = *(const float4*)(B + (size_t)(k0+br)*N + n0 + bc);
        __syncthreads();
#pragma unroll
        for (int k=0;k<16;k++){
            float4 a0 = *(const float4*)&As[k][ty*8];
            float4 a1 = *(const float4*)&As[k][ty*8+4];
            float4 b0 = *(const float4*)&Bs[k][tx*4];
            float ra[8]={a0.x,a0.y,a0.z,a0.w,a1.x,a1.y,a1.z,a1.w};
            float rb[4]={b0.x,b0.y,b0.z,b0.w};
#pragma unroll
            for (int i=0;i<8;i++)
#pragma unroll
                for (int j=0;j<4;j++) acc[i][j] += ra[i]*rb[j];
        }
        __syncthreads();
    }
    const int col = n0 + tx*4;
    float bb0=0.f,bb1=0.f,bb2=0.f,bb3=0.f;
    if (bias){ float4 bv = *(const float4*)(bias+col); bb0=bv.x;bb1=bv.y;bb2=bv.z;bb3=bv.w; }
#pragma unroll
    for (int i=0;i<8;i++){
        int row = m0 + ty*8 + i;
        float v0=acc[i][0]+bb0, v1=acc[i][1]+bb1, v2=acc[i][2]+bb2, v3=acc[i][3]+bb3;
        if (OP==1){ v0=geluf(v0); v1=geluf(v1); v2=geluf(v2); v3=geluf(v3); }
        if (OP==3){ float4 rv = *(const float4*)(R + (size_t)row*N + col);
                    v0+=rv.x; v1+=rv.y; v2+=rv.z; v3+=rv.w; }
        if (OP==2 && col < 256){
            int l = row & 511;
            const float* ct = (col<128)? g_qc : g_kc;
            const float* st = (col<128)? g_qs : g_ks;
            int j0 = (col&31)>>1, j1 = ((col+2)&31)>>1;
            float c0=ct[l*16+j0], s0=st[l*16+j0], c1=ct[l*16+j1], s1=st[l*16+j1];
            float t0=v0*c0-v1*s0, t1=v1*c0+v0*s0, t2=v2*c1-v3*s1, t3=v3*c1+v2*s1;
            v0=t0; v1=t1; v2=t2; v3=t3;
        }
        *(float4*)(C + (size_t)row*N + col) = make_float4(v0,v1,v2,v3);
    }
}

// ------------------- Retention + group-norm + silu gate -------------------
__global__ __launch_bounds__(256) void retention_kernel(
    const float* __restrict__ QKVG, const float* __restrict__ gn_w,
    const float* __restrict__ gn_b, float* __restrict__ P)
{
    __shared__ float Qt[32][64], Kt[32][64], Vs[64][64], Ss[64][64];
    const int tid = threadIdx.x, tx = tid&15, ty = tid>>4;
    const int lt = blockIdx.x, h = blockIdx.y, b = blockIdx.z;
    const int l0 = lt*64;
    const size_t rb = (size_t)b*512;

    const double lgA = -3.4657359027997265, lgB = -6.2383246250395075;
    const float lg2g = (float)(log(1.0 - exp(lgA + (lgB-lgA)*(double)h/3.0)) * 1.4426950408889634);

    const int qrow = tid>>2, qc8 = (tid&3)*8, vc16 = (tid&3)*16;
    {   // Q tile, scaled by gamma^i
        const float* src = QKVG + (rb + l0 + qrow)*QKN + h*32 + qc8;
        float sc = exp2f((float)qrow * lg2g);
        float4 v0 = *(const float4*)src, v1 = *(const float4*)(src+4);
        Qt[qc8+0][qrow]=v0.x*sc; Qt[qc8+1][qrow]=v0.y*sc; Qt[qc8+2][qrow]=v0.z*sc; Qt[qc8+3][qrow]=v0.w*sc;
        Qt[qc8+4][qrow]=v1.x*sc; Qt[qc8+5][qrow]=v1.y*sc; Qt[qc8+6][qrow]=v1.z*sc; Qt[qc8+7][qrow]=v1.w*sc;
    }
    float y[4][4] = {};

    for (int mt=0; mt<=lt; mt++){
        int m0 = mt*64;
        {   // K tile (gamma^(l0-m0-j)) + V tile
            const float* ks = QKVG + (rb + m0 + qrow)*QKN + 128 + h*32 + qc8;
            float sc = exp2f((float)(l0 - m0 - qrow) * lg2g);
            float4 v0 = *(const float4*)ks, v1 = *(const float4*)(ks+4);
            Kt[qc8+0][qrow]=v0.x*sc; Kt[qc8+1][qrow]=v0.y*sc; Kt[qc8+2][qrow]=v0.z*sc; Kt[qc8+3][qrow]=v0.w*sc;
            Kt[qc8+4][qrow]=v1.x*sc; Kt[qc8+5][qrow]=v1.y*sc; Kt[qc8+6][qrow]=v1.z*sc; Kt[qc8+7][qrow]=v1.w*sc;
            const float* vs = QKVG + (rb + m0 + qrow)*QKN + 256 + h*64 + vc16;
#pragma unroll
            for (int u=0;u<4;u++) *(float4*)&Vs[qrow][vc16+u*4] = *(const float4*)(vs+u*4);
        }
        __syncthreads();
        float s[4][4] = {};
#pragma unroll
        for (int d=0; d<32; d++){
            float4 qa = *(const float4*)&Qt[d][ty*4];
            float4 kb = *(const float4*)&Kt[d][tx*4];
            float qr[4]={qa.x,qa.y,qa.z,qa.w}, kr[4]={kb.x,kb.y,kb.z,kb.w};
#pragma unroll
            for (int ii=0;ii<4;ii++)
#pragma unroll
                for (int jj=0;jj<4;jj++) s[ii][jj] += qr[ii]*kr[jj];
        }
        if (mt == lt){
#pragma unroll
            for (int ii=0;ii<4;ii++)
#pragma unroll
                for (int jj=0;jj<4;jj++)
                    if (ty*4+ii < tx*4+jj) s[ii][jj] = 0.f;
        }
#pragma unroll
        for (int ii=0;ii<4;ii++)
            *(float4*)&Ss[ty*4+ii][tx*4] = make_float4(s[ii][0],s[ii][1],s[ii][2],s[ii][3]);
        __syncthreads();
#pragma unroll 8
        for (int j=0;j<64;j++){
            float4 vb = *(const float4*)&Vs[j][tx*4];
            float vr[4]={vb.x,vb.y,vb.z,vb.w};
            float a0=Ss[ty*4+0][j], a1=Ss[ty*4+1][j], a2=Ss[ty*4+2][j], a3=Ss[ty*4+3][j];
#pragma unroll
            for (int vv=0;vv<4;vv++){
                y[0][vv]+=a0*vr[vv]; y[1][vv]+=a1*vr[vv];
                y[2][vv]+=a2*vr[vv]; y[3][vv]+=a3*vr[vv];
            }
        }
        __syncthreads();
    }
#pragma unroll
    for (int ii=0;ii<4;ii++)
        *(float4*)&Ss[ty*4+ii][tx*4] = make_float4(y[ii][0],y[ii][1],y[ii][2],y[ii][3]);
    __syncthreads();

    const int r = tid>>2, q = tid&3;
    float sum=0.f, ssq=0.f;
#pragma unroll
    for (int u=0;u<4;u++){
        float4 v = *(const float4*)&Ss[r][q*16+u*4];
        sum += v.x+v.y+v.z+v.w;
        ssq += v.x*v.x+v.y*v.y+v.z*v.z+v.w*v.w;
    }
    sum += __shfl_xor_sync(~0u,sum,1); ssq += __shfl_xor_sync(~0u,ssq,1);
    sum += __shfl_xor_sync(~0u,sum,2); ssq += __shfl_xor_sync(~0u,ssq,2);
    float mean = sum*(1.f/64.f), var = ssq*(1.f/64.f)-mean*mean;
    float rstd = rsqrtf(var + 1e-5f);
    const float* gs = QKVG + (rb + l0 + r)*QKN + 512 + h*64 + q*16;
    const float* gw = gn_w + h*64 + q*16;
    const float* gb = gn_b + h*64 + q*16;
    float* dst = P + (rb + l0 + r)*VD + h*64 + q*16;
#pragma unroll
    for (int u=0;u<4;u++){
        float4 yv = *(const float4*)&Ss[r][q*16+u*4];
        float4 gv = *(const float4*)(gs+u*4);
        float4 wv = *(const float4*)(gw+u*4);
        float4 bv = *(const float4*)(gb+u*4);
        float4 o;
        o.x = ((yv.x-mean)*rstd*wv.x+bv.x)*siluf(gv.x);
        o.y = ((yv.y-mean)*rstd*wv.y+bv.y)*siluf(gv.y);
        o.z = ((yv.z-mean)*rstd*wv.z+bv.z)*siluf(gv.z);
        o.w = ((yv.w-mean)*rstd*wv.w+bv.w)*siluf(gv.w);
        *(float4*)(dst+u*4) = o;
    }
}

// ------------------- decoder + softmax -------------------
__global__ __launch_bounds__(256) void dec_kernel(
    const float* __restrict__ X, const float* __restrict__ w1, const float* __restrict__ b1,
    const float* __restrict__ w2, const float* __restrict__ b2, float* __restrict__ out)
{
    __shared__ float sw1[8192], sw2[1280], sb1[64], sb2[20];
    int tid = threadIdx.x;
    for (int i=tid;i<8192;i+=256) sw1[i]=w1[i];
    for (int i=tid;i<1280;i+=256) sw2[i]=w2[i];
    if (tid<64) sb1[tid]=b1[tid];
    if (tid<20) sb2[tid]=b2[tid];
    __syncthreads();
    int t = blockIdx.x*256 + tid;
    float h[64];
#pragma unroll
    for (int o=0;o<64;o++) h[o]=sb1[o];
    for (int k=0;k<128;k+=4){
        float4 xv = *(const float4*)(X + (size_t)t*128 + k);
#pragma unroll
        for (int o=0;o<64;o++){
            h[o] += xv.x*sw1[(k+0)*64+o] + xv.y*sw1[(k+1)*64+o]
                  + xv.z*sw1[(k+2)*64+o] + xv.w*sw1[(k+3)*64+o];
        }
    }
#pragma unroll
    for (int o=0;o<64;o++) h[o]=geluf(h[o]);
    float lg[20];
#pragma unroll
    for (int o=0;o<20;o++){ float s=sb2[o];
#pragma unroll
        for (int k=0;k<64;k++) s += h[k]*sw2[k*20+o];
        lg[o]=s; }
    float mx = lg[0];
#pragma unroll
    for (int o=1;o<20;o++) mx = fmaxf(mx, lg[o]);
    float sum = 0.f;
#pragma unroll
    for (int o=0;o<20;o++){ lg[o] = expf(lg[o]-mx); sum += lg[o]; }
    float inv = 1.0f/sum;
#pragma unroll
    for (int o=0;o<20;o++) out[(size_t)t*20+o] = lg[o]*inv;
}

// ------------------- launch -------------------
extern "C" void kernel_launch(void* const* d_in, const int* in_sizes, int n_in,
                              void* d_out, int out_size)
{
    const float* x      = (const float*)d_in[0];
    const float* rem_w1 = (const float*)d_in[1];
    const float* rem_b1 = (const float*)d_in[2];
    const float* rem_w2 = (const float*)d_in[3];
    const float* rem_b2 = (const float*)d_in[4];
    const float* rem_w3 = (const float*)d_in[5];
    const float* rem_b3 = (const float*)d_in[6];
    const float* wq     = (const float*)d_in[7];
    const float* wk     = (const float*)d_in[8];
    const float* wv     = (const float*)d_in[9];
    const float* wg     = (const float*)d_in[10];
    const float* wo     = (const float*)d_in[11];
    const float* gn_w   = (const float*)d_in[12];
    const float* gn_b   = (const float*)d_in[13];
    const float* ln1_w  = (const float*)d_in[14];
    const float* ln1_b  = (const float*)d_in[15];
    const float* ln2_w  = (const float*)d_in[16];
    const float* ln2_b  = (const float*)d_in[17];
    const float* ffn_w1 = (const float*)d_in[18];
    const float* ffn_b1 = (const float*)d_in[19];
    const float* ffn_w2 = (const float*)d_in[20];
    const float* ffn_b2 = (const float*)d_in[21];
    const float* dec_w1 = (const float*)d_in[22];
    const float* dec_b1 = (const float*)d_in[23];
    const float* dec_w2 = (const float*)d_in[24];
    const float* dec_b2 = (const float*)d_in[25];
    float* out = (float*)d_out;

    float *pX, *pXn, *pY1, *pQK, *pP, *pHf, *pW;
    cudaGetSymbolAddress((void**)&pX,  g_X);
    cudaGetSymbolAddress((void**)&pXn, g_Xn);
    cudaGetSymbolAddress((void**)&pY1, g_Y1);
    cudaGetSymbolAddress((void**)&pQK, g_QK);
    cudaGetSymbolAddress((void**)&pP,  g_P);
    cudaGetSymbolAddress((void**)&pHf, g_Hf);
    cudaGetSymbolAddress((void**)&pW,  g_W);

    xpos_table_kernel<<<32, 256>>>();
    pack_w_kernel<<<(4*HID*QKN + 255)/256, 256>>>(wq, wk, wv, wg);
    rem_kernel<<<TOKENS/256, 256>>>(x, rem_w1, rem_b1, rem_w2, rem_b2, rem_w3, rem_b3, pX);

    for (int l = 0; l < 4; l++) {
        ln_kernel<<<TOKENS/8, 256>>>(pX, ln1_w + l*128, ln1_b + l*128, pXn);
        gemm_kernel<2><<<dim3(QKN/64, TOKENS/128), 256>>>(
            pXn, pW + (size_t)l*HID*QKN, nullptr, nullptr, pQK, TOKENS, QKN, HID);
        retention_kernel<<<dim3(8, 4, 64), 256>>>(pQK, gn_w + l*VD, gn_b + l*VD, pP);
        gemm_kernel<3><<<dim3(HID/64, TOKENS/128), 256>>>(
            pP, wo + (size_t)l*VD*HID, nullptr, pX, pY1, TOKENS, HID, VD);
        ln_kernel<<<TOKENS/8, 256>>>(pY1, ln2_w + l*128, ln2_b + l*128, pXn);
        gemm_kernel<1><<<dim3(FFND/64, TOKENS/128), 256>>>(
            pXn, ffn_w1 + (size_t)l*HID*FFND, ffn_b1 + l*FFND, nullptr, pHf, TOKENS, FFND, HID);
        gemm_kernel<3><<<dim3(HID/64, TOKENS/128), 256>>>(
            pHf, ffn_w2 + (size_t)l*FFND*HID, ffn_b2 + l*HID, pY1, pX, TOKENS, HID, FFND);
    }
    dec_kernel<<<TOKENS/256, 256>>>(pX, dec_w1, dec_b1, dec_w2, dec_b2, out);
}